// round 12
// baseline (speedup 1.0000x reference)
#include <cuda_runtime.h>
#include <math.h>

#define NUM_CLASSES 722
#define NV2 361              // float2 elements per row
#define N_ROWS 65536         // 32 * 2048
#define THREADS 256
#define WARPS 8
#define GRID 444             // 148 SMs * 3 blocks (85-reg ceiling) -> one uniform wave
#define TOTAL_WARPS (GRID * WARPS)   // 3552

// DECAYS[d] = exp(-(2^d)/4)
__constant__ float c_decay[4] = {
    0.7788007830714049f,   // unused at c==t (exact hit -> 1.0)
    0.6065306597126334f,
    0.36787944117144233f,
    0.1353352832366127f
};

__device__ float g_partial[GRID];
__device__ unsigned int g_count = 0;

__device__ __forceinline__ float warpSum(float v) {
#pragma unroll
    for (int o = 16; o; o >>= 1) v += __shfl_xor_sync(0xffffffffu, v, o);
    return v;
}
// Sum over 8-lane group (lanes 0..7 hold data; others contribute 0).
__device__ __forceinline__ float groupSum8(float v) {
    v += __shfl_xor_sync(0xffffffffu, v, 4);
    v += __shfl_xor_sync(0xffffffffu, v, 2);
    v += __shfl_xor_sync(0xffffffffu, v, 1);
    return v;
}

__global__ __launch_bounds__(THREADS, 3)
void ce_fused_kernel(const float* __restrict__ pred, const int* __restrict__ target,
                     float* __restrict__ out) {
    __shared__ float sh[WARPS];
    __shared__ unsigned int s_last;

    const int tid  = threadIdx.x;
    const int warp = tid >> 5;
    const int lane = tid & 31;
    const int gw   = blockIdx.x * WARPS + warp;

    float acc = 0.0f;    // only lane 0's value is meaningful

    // ---- register ping-pong buffers: prefetch row r+stride while computing row r ----
    float2 A[12], B[12];

    auto load_row = [&](float2 (&buf)[12], int row) {
        const float2* rp = reinterpret_cast<const float2*>(pred + (size_t)row * NUM_CLASSES);
#pragma unroll
        for (int k = 0; k < 11; ++k) buf[k] = __ldg(rp + lane + 32 * k);
        buf[11] = (lane < 9) ? __ldg(rp + lane + 352) : make_float2(0.f, 0.f);
    };

    auto process = [&](const float2 (&buf)[12], int row) -> float {
        const int t = __ldg(target + row);

        // sum of exp
        float se = 0.0f;
#pragma unroll
        for (int k = 0; k < 11; ++k) se += __expf(buf[k].x) + __expf(buf[k].y);
        if (lane < 9) se += __expf(buf[11].x) + __expf(buf[11].y);

        // analytic weight sum
        float sw = 1.0f;
#pragma unroll
        for (int d = 1; d <= 3; ++d) {
            const float dd = c_decay[d];
            sw += ((t - d >= 0) ? dd : 0.f) + ((t + d <= NUM_CLASSES - 1) ? dd : 0.f);
        }

        // sparse dot via L1-hit reloads: lanes 0..6 own offsets t-3..t+3
        float swv = 0.0f;
        if (lane < 7) {
            const int d = lane - 3;
            const float w = (d == 0) ? 1.0f : c_decay[(d < 0) ? -d : d];
            const int c = t + d;
            if (c >= 0 && c < NUM_CLASSES)
                swv = w * __ldg(pred + (size_t)row * NUM_CLASSES + c);
        }

        se  = warpSum(se);
        swv = groupSum8(swv);     // lane 0 valid
        return sw * __logf(se) - swv;
    };

    int r = gw;                   // gw < 3552 < N_ROWS always
    load_row(A, r);
    bool curA = true;
    while (r < N_ROWS) {
        const int rn = r + TOTAL_WARPS;
        if (curA) {
            if (rn < N_ROWS) load_row(B, rn);   // prefetch while computing A
            acc += process(A, r);
        } else {
            if (rn < N_ROWS) load_row(A, rn);
            acc += process(B, r);
        }
        curA = !curA;
        r = rn;
    }

    // ---- block partial (lane 0 per warp; fixed order -> deterministic) ----
    if (lane == 0) sh[warp] = acc;
    __syncthreads();
    if (tid == 0) {
        float psum = 0.0f;
#pragma unroll
        for (int i = 0; i < WARPS; ++i) psum += sh[i];
        g_partial[blockIdx.x] = psum;
        __threadfence();
        unsigned int old = atomicAdd(&g_count, 1u);
        s_last = (old == GRID - 1) ? 1u : 0u;
    }
    __syncthreads();

    // ---- last block: deterministic final reduce + counter reset ----
    if (s_last) {
        float v = 0.0f;
        for (int i = tid; i < GRID; i += THREADS) v += g_partial[i];
        v = warpSum(v);
        if (lane == 0) sh[warp] = v;
        __syncthreads();
        if (tid == 0) {
            float x = 0.0f;
#pragma unroll
            for (int i = 0; i < WARPS; ++i) x += sh[i];
            out[0] = x * (1.0f / (float)N_ROWS);
            g_count = 0;   // reset for next graph replay
        }
    }
}

extern "C" void kernel_launch(void* const* d_in, const int* in_sizes, int n_in,
                              void* d_out, int out_size) {
    const float* pred   = (const float*)d_in[0];
    const int*   target = (const int*)d_in[1];
    float*       out    = (float*)d_out;

    ce_fused_kernel<<<GRID, THREADS>>>(pred, target, out);
}